// round 1
// baseline (speedup 1.0000x reference)
#include <cuda_runtime.h>

#define NN 50000
#define DIM 64
#define NE 800000

// ---------------- scratch (allocation-free: device globals) ----------------
__device__ __align__(16) float g_x0  [NN * DIM];   // normalized input
__device__ __align__(16) float g_ping[NN * DIM];   // layer-1 output
__device__ __align__(16) float g_res0[NN * DIM];   // graph 0 layer-2 output
__device__ __align__(16) float g_res1[NN * DIM];
__device__ __align__(16) float g_res2[NN * DIM];
__device__ float g_deg [NN];
__device__ float g_dinv[NN];
__device__ float g_en  [NE];                        // per-edge norm

__device__ __forceinline__ float* buf(int id) {
    switch (id) {
        case 0:  return g_x0;
        case 1:  return g_ping;
        case 2:  return g_res0;
        case 3:  return g_res1;
        default: return g_res2;
    }
}

// ---------------- kernels ----------------

// L2-normalize input rows -> g_x0. One warp per row, 2 floats per lane.
__global__ void k_l2norm_in(const float* __restrict__ x) {
    int warp = (blockIdx.x * blockDim.x + threadIdx.x) >> 5;
    int lane = threadIdx.x & 31;
    if (warp >= NN) return;
    int off = warp * DIM + lane * 2;
    float2 v = *(const float2*)(x + off);
    float s = v.x * v.x + v.y * v.y;
    #pragma unroll
    for (int o = 16; o; o >>= 1) s += __shfl_xor_sync(0xFFFFFFFFu, s, o);
    float inv = 1.0f / fmaxf(sqrtf(s), 1e-12f);
    float2 r = make_float2(v.x * inv, v.y * inv);
    *(float2*)(g_x0 + off) = r;
}

__global__ void k_zero_vec(int id) {
    int i = blockIdx.x * blockDim.x + threadIdx.x;
    if (i < NN * DIM / 4)
        ((float4*)buf(id))[i] = make_float4(0.f, 0.f, 0.f, 0.f);
}

__global__ void k_zero_deg() {
    int i = blockIdx.x * blockDim.x + threadIdx.x;
    if (i < NN) g_deg[i] = 0.f;
}

__global__ void k_degree(const int* __restrict__ dst) {
    int e = blockIdx.x * blockDim.x + threadIdx.x;
    if (e < NE) atomicAdd(&g_deg[dst[e]], 1.0f);
}

__global__ void k_dinv() {
    int i = blockIdx.x * blockDim.x + threadIdx.x;
    if (i >= NN) return;
    float d = g_deg[i];
    g_dinv[i] = (d > 0.f) ? rsqrtf(d) : 0.f;
}

__global__ void k_edge_norm(const int* __restrict__ src, const int* __restrict__ dst) {
    int e = blockIdx.x * blockDim.x + threadIdx.x;
    if (e >= NE) return;
    g_en[e] = g_dinv[src[e]] * g_dinv[dst[e]];
}

// Scatter: y[dst] += norm[e] * x[src]. 16 threads per edge, float4 per thread.
__global__ void k_scatter(const int* __restrict__ src, const int* __restrict__ dst,
                          int in_id, int out_id) {
    int idx = blockIdx.x * blockDim.x + threadIdx.x;
    int e = idx >> 4;
    if (e >= NE) return;
    float nm = g_en[e];
    if (nm == 0.f) return;
    int q = (idx & 15) * 4;
    const float* xin = buf(in_id);
    float*       yo  = buf(out_id);
    int s = __ldg(src + e);
    int d = __ldg(dst + e);
    float4 v = *(const float4*)(xin + s * DIM + q);
    float* o = yo + d * DIM + q;
    atomicAdd(o + 0, nm * v.x);
    atomicAdd(o + 1, nm * v.y);
    atomicAdd(o + 2, nm * v.z);
    atomicAdd(o + 3, nm * v.w);
}

// Fused: normalize each of the 3 results per row and weighted-combine.
__global__ void k_combine(const float* __restrict__ alpha, float* __restrict__ out) {
    int warp = (blockIdx.x * blockDim.x + threadIdx.x) >> 5;
    int lane = threadIdx.x & 31;
    if (warp >= NN) return;

    // weights: softmax(alpha) -> clip(1e-4) -> renormalize
    float a0 = alpha[0], a1 = alpha[1], a2 = alpha[2];
    float m  = fmaxf(a0, fmaxf(a1, a2));
    float e0 = expf(a0 - m), e1 = expf(a1 - m), e2 = expf(a2 - m);
    float s3 = e0 + e1 + e2;
    float w0 = fmaxf(e0 / s3, 1e-4f);
    float w1 = fmaxf(e1 / s3, 1e-4f);
    float w2 = fmaxf(e2 / s3, 1e-4f);
    float ws = w0 + w1 + w2;
    w0 /= ws; w1 /= ws; w2 /= ws;

    int off = warp * DIM + lane * 2;
    float2 va = *(const float2*)(g_res0 + off);
    float2 vb = *(const float2*)(g_res1 + off);
    float2 vc = *(const float2*)(g_res2 + off);
    float sa = va.x * va.x + va.y * va.y;
    float sb = vb.x * vb.x + vb.y * vb.y;
    float sc = vc.x * vc.x + vc.y * vc.y;
    #pragma unroll
    for (int o = 16; o; o >>= 1) {
        sa += __shfl_xor_sync(0xFFFFFFFFu, sa, o);
        sb += __shfl_xor_sync(0xFFFFFFFFu, sb, o);
        sc += __shfl_xor_sync(0xFFFFFFFFu, sc, o);
    }
    float ia = 1.0f / fmaxf(sqrtf(sa), 1e-12f);
    float ib = 1.0f / fmaxf(sqrtf(sb), 1e-12f);
    float ic = 1.0f / fmaxf(sqrtf(sc), 1e-12f);

    float2 r;
    r.x = w0 * va.x * ia + w1 * vb.x * ib + w2 * vc.x * ic;
    r.y = w0 * va.y * ia + w1 * vb.y * ib + w2 * vc.y * ic;
    *(float2*)(out + off) = r;
}

// ---------------- launch ----------------
extern "C" void kernel_launch(void* const* d_in, const int* in_sizes, int n_in,
                              void* d_out, int out_size) {
    const float* x     = (const float*)d_in[0];
    const float* alpha = (const float*)d_in[1];
    const int*   ei[3] = { (const int*)d_in[2], (const int*)d_in[3], (const int*)d_in[4] };
    float* out = (float*)d_out;

    const int T = 256;
    const int gRows  = (NN * 32 + T - 1) / T;     // one warp per row
    const int gNodes = (NN + T - 1) / T;
    const int gEdges = (NE + T - 1) / T;
    const int gScat  = (NE * 16 + T - 1) / T;
    const int gZero  = (NN * DIM / 4 + T - 1) / T;

    k_l2norm_in<<<gRows, T>>>(x);

    for (int g = 0; g < 3; g++) {
        const int* src = ei[g];            // edge_index[0]
        const int* dst = ei[g] + NE;       // edge_index[1]

        k_zero_deg<<<gNodes, T>>>();
        k_degree  <<<gEdges, T>>>(dst);
        k_dinv    <<<gNodes, T>>>();
        k_edge_norm<<<gEdges, T>>>(src, dst);

        // layer 1: x0 -> ping
        k_zero_vec<<<gZero, T>>>(1);
        k_scatter <<<gScat, T>>>(src, dst, 0, 1);
        // layer 2: ping -> res[g]
        k_zero_vec<<<gZero, T>>>(2 + g);
        k_scatter <<<gScat, T>>>(src, dst, 1, 2 + g);
    }

    k_combine<<<gRows, T>>>(alpha, out);
}

// round 2
// speedup vs baseline: 1.8650x; 1.8650x over previous
#include <cuda_runtime.h>

#define NN 50000
#define DIM 64
#define NE 800000

// ---------------- scratch (allocation-free: device globals) ----------------
__device__ __align__(16) float g_x0  [NN * DIM];   // normalized input
__device__ __align__(16) float g_ping[NN * DIM];   // layer-1 output
__device__ __align__(16) float g_res0[NN * DIM];   // graph 0 layer-2 output
__device__ __align__(16) float g_res1[NN * DIM];
__device__ __align__(16) float g_res2[NN * DIM];
__device__ float g_deg [NN];
__device__ float g_dinv[NN];

__device__ __forceinline__ float* buf(int id) {
    switch (id) {
        case 0:  return g_x0;
        case 1:  return g_ping;
        case 2:  return g_res0;
        case 3:  return g_res1;
        default: return g_res2;
    }
}

// ---------------- kernels ----------------

// L2-normalize input rows -> g_x0. One warp per row, 2 floats per lane.
__global__ void k_l2norm_in(const float* __restrict__ x) {
    int warp = (blockIdx.x * blockDim.x + threadIdx.x) >> 5;
    int lane = threadIdx.x & 31;
    if (warp >= NN) return;
    int off = warp * DIM + lane * 2;
    float2 v = *(const float2*)(x + off);
    float s = v.x * v.x + v.y * v.y;
    #pragma unroll
    for (int o = 16; o; o >>= 1) s += __shfl_xor_sync(0xFFFFFFFFu, s, o);
    float inv = 1.0f / fmaxf(sqrtf(s), 1e-12f);
    float2 r = make_float2(v.x * inv, v.y * inv);
    *(float2*)(g_x0 + off) = r;
}

__global__ void k_zero_vec(int id) {
    int i = blockIdx.x * blockDim.x + threadIdx.x;
    if (i < NN * DIM / 4)
        ((float4*)buf(id))[i] = make_float4(0.f, 0.f, 0.f, 0.f);
}

__global__ void k_zero_deg() {
    int i = blockIdx.x * blockDim.x + threadIdx.x;
    if (i < NN) g_deg[i] = 0.f;
}

__global__ void k_degree(const int* __restrict__ dst) {
    int e = blockIdx.x * blockDim.x + threadIdx.x;
    if (e < NE) atomicAdd(&g_deg[dst[e]], 1.0f);
}

__global__ void k_dinv() {
    int i = blockIdx.x * blockDim.x + threadIdx.x;
    if (i >= NN) return;
    float d = g_deg[i];
    g_dinv[i] = (d > 0.f) ? rsqrtf(d) : 0.f;
}

// Scatter: y[dst] += dinv[src]*dinv[dst] * x[src].
// 16 threads per edge, one float4 gather + one red.global.add.v4.f32 each.
__global__ void k_scatter(const int* __restrict__ src, const int* __restrict__ dst,
                          int in_id, int out_id) {
    int idx = blockIdx.x * blockDim.x + threadIdx.x;
    int e = idx >> 4;
    if (e >= NE) return;
    int s = __ldg(src + e);
    int d = __ldg(dst + e);
    float nm = __ldg(g_dinv + s) * __ldg(g_dinv + d);   // broadcast within 16-thread group
    int q = (idx & 15) * 4;
    const float* xin = buf(in_id);
    float*       yo  = buf(out_id);
    float4 v = *(const float4*)(xin + s * DIM + q);
    float* o = yo + d * DIM + q;
    asm volatile("red.global.add.v4.f32 [%0], {%1, %2, %3, %4};"
                 :: "l"(o), "f"(nm * v.x), "f"(nm * v.y), "f"(nm * v.z), "f"(nm * v.w)
                 : "memory");
}

// Fused: normalize each of the 3 results per row and weighted-combine.
__global__ void k_combine(const float* __restrict__ alpha, float* __restrict__ out) {
    int warp = (blockIdx.x * blockDim.x + threadIdx.x) >> 5;
    int lane = threadIdx.x & 31;
    if (warp >= NN) return;

    // weights: softmax(alpha) -> clip(1e-4) -> renormalize
    float a0 = alpha[0], a1 = alpha[1], a2 = alpha[2];
    float m  = fmaxf(a0, fmaxf(a1, a2));
    float e0 = expf(a0 - m), e1 = expf(a1 - m), e2 = expf(a2 - m);
    float s3 = e0 + e1 + e2;
    float w0 = fmaxf(e0 / s3, 1e-4f);
    float w1 = fmaxf(e1 / s3, 1e-4f);
    float w2 = fmaxf(e2 / s3, 1e-4f);
    float ws = w0 + w1 + w2;
    w0 /= ws; w1 /= ws; w2 /= ws;

    int off = warp * DIM + lane * 2;
    float2 va = *(const float2*)(g_res0 + off);
    float2 vb = *(const float2*)(g_res1 + off);
    float2 vc = *(const float2*)(g_res2 + off);
    float sa = va.x * va.x + va.y * va.y;
    float sb = vb.x * vb.x + vb.y * vb.y;
    float sc = vc.x * vc.x + vc.y * vc.y;
    #pragma unroll
    for (int o = 16; o; o >>= 1) {
        sa += __shfl_xor_sync(0xFFFFFFFFu, sa, o);
        sb += __shfl_xor_sync(0xFFFFFFFFu, sb, o);
        sc += __shfl_xor_sync(0xFFFFFFFFu, sc, o);
    }
    float ia = 1.0f / fmaxf(sqrtf(sa), 1e-12f);
    float ib = 1.0f / fmaxf(sqrtf(sb), 1e-12f);
    float ic = 1.0f / fmaxf(sqrtf(sc), 1e-12f);

    float2 r;
    r.x = w0 * va.x * ia + w1 * vb.x * ib + w2 * vc.x * ic;
    r.y = w0 * va.y * ia + w1 * vb.y * ib + w2 * vc.y * ic;
    *(float2*)(out + off) = r;
}

// ---------------- launch ----------------
extern "C" void kernel_launch(void* const* d_in, const int* in_sizes, int n_in,
                              void* d_out, int out_size) {
    const float* x     = (const float*)d_in[0];
    const float* alpha = (const float*)d_in[1];
    const int*   ei[3] = { (const int*)d_in[2], (const int*)d_in[3], (const int*)d_in[4] };
    float* out = (float*)d_out;

    const int T = 256;
    const int gRows  = (NN * 32 + T - 1) / T;     // one warp per row
    const int gNodes = (NN + T - 1) / T;
    const int gEdges = (NE + T - 1) / T;
    const int gScat  = (NE * 16 + T - 1) / T;
    const int gZero  = (NN * DIM / 4 + T - 1) / T;

    k_l2norm_in<<<gRows, T>>>(x);

    for (int g = 0; g < 3; g++) {
        const int* src = ei[g];            // edge_index[0]
        const int* dst = ei[g] + NE;       // edge_index[1]

        k_zero_deg<<<gNodes, T>>>();
        k_degree  <<<gEdges, T>>>(dst);
        k_dinv    <<<gNodes, T>>>();

        // layer 1: x0 -> ping
        k_zero_vec<<<gZero, T>>>(1);
        k_scatter <<<gScat, T>>>(src, dst, 0, 1);
        // layer 2: ping -> res[g]
        k_zero_vec<<<gZero, T>>>(2 + g);
        k_scatter <<<gScat, T>>>(src, dst, 1, 2 + g);
    }

    k_combine<<<gRows, T>>>(alpha, out);
}

// round 3
// speedup vs baseline: 3.3927x; 1.8191x over previous
#include <cuda_runtime.h>

#define NN 50000
#define DIM 64
#define NE 800000

// ---------------- scratch (allocation-free: device globals) ----------------
__device__ __align__(16) float g_x0  [NN * DIM];       // normalized input (shared by all graphs)
__device__ __align__(16) float g_ping[3][NN * DIM];    // layer-1 outputs
__device__ __align__(16) float g_res [3][NN * DIM];    // layer-2 outputs
__device__ int   g_degi  [3][NN];
__device__ int   g_cursor[3][NN];
__device__ int   g_off   [3][NN + 1];
__device__ float g_dinv  [3][NN];
__device__ int   g_csr   [3][NE];

// ---------------- kernels ----------------

// L2-normalize input rows -> g_x0. One warp per row, 2 floats per lane.
__global__ void k_l2norm_in(const float* __restrict__ x) {
    int warp = (blockIdx.x * blockDim.x + threadIdx.x) >> 5;
    int lane = threadIdx.x & 31;
    if (warp >= NN) return;
    int off = warp * DIM + lane * 2;
    float2 v = *(const float2*)(x + off);
    float s = v.x * v.x + v.y * v.y;
    #pragma unroll
    for (int o = 16; o; o >>= 1) s += __shfl_xor_sync(0xFFFFFFFFu, s, o);
    float inv = 1.0f / fmaxf(sqrtf(s), 1e-12f);
    *(float2*)(g_x0 + off) = make_float2(v.x * inv, v.y * inv);
}

// Zero degree + cursor for all 3 graphs.
__global__ void k_zero_int() {
    int i = blockIdx.x * blockDim.x + threadIdx.x;
    if (i < 3 * NN) {
        ((int*)g_degi)[i]   = 0;
        ((int*)g_cursor)[i] = 0;
    }
}

// Degree of dst for all 3 graphs.
__global__ void k_degree3(const int* __restrict__ d0, const int* __restrict__ d1,
                          const int* __restrict__ d2) {
    int i = blockIdx.x * blockDim.x + threadIdx.x;
    if (i >= 3 * NE) return;
    int g = i / NE, e = i - g * NE;
    const int* d = (g == 0) ? d0 : (g == 1) ? d1 : d2;
    atomicAdd(&g_degi[g][__ldg(d + e)], 1);
}

// Exclusive prefix scan of degrees (one block per graph) + dinv.
__global__ void k_scan() {
    int g    = blockIdx.x;
    int tid  = threadIdx.x;
    int lane = tid & 31, wid = tid >> 5;
    __shared__ int wsum[32];
    __shared__ int s_carry;
    if (tid == 0) s_carry = 0;
    __syncthreads();

    for (int base = 0; base < NN; base += 1024) {
        int i = base + tid;
        int v = (i < NN) ? g_degi[g][i] : 0;
        int incl = v;
        #pragma unroll
        for (int o = 1; o < 32; o <<= 1) {
            int t = __shfl_up_sync(0xFFFFFFFFu, incl, o);
            if (lane >= o) incl += t;
        }
        if (lane == 31) wsum[wid] = incl;
        __syncthreads();
        if (wid == 0) {
            int s = wsum[lane];
            #pragma unroll
            for (int o = 1; o < 32; o <<= 1) {
                int t = __shfl_up_sync(0xFFFFFFFFu, s, o);
                if (lane >= o) s += t;
            }
            wsum[lane] = s;
        }
        __syncthreads();
        int warp_off = (wid > 0) ? wsum[wid - 1] : 0;
        int tile_tot = wsum[31];
        if (i < NN) {
            g_off[g][i]  = s_carry + warp_off + incl - v;
            g_dinv[g][i] = (v > 0) ? rsqrtf((float)v) : 0.f;
        }
        __syncthreads();
        if (tid == 0) s_carry += tile_tot;
        __syncthreads();
    }
    if (tid == 0) g_off[g][NN] = s_carry;
}

// Counting-sort fill: csr[g][ off[dst] + cursor[dst]++ ] = src.
__global__ void k_fill3(const int* __restrict__ s0, const int* __restrict__ d0,
                        const int* __restrict__ s1, const int* __restrict__ d1,
                        const int* __restrict__ s2, const int* __restrict__ d2) {
    int i = blockIdx.x * blockDim.x + threadIdx.x;
    if (i >= 3 * NE) return;
    int g = i / NE, e = i - g * NE;
    const int* s = (g == 0) ? s0 : (g == 1) ? s1 : s2;
    const int* d = (g == 0) ? d0 : (g == 1) ? d1 : d2;
    int dn  = __ldg(d + e);
    int pos = g_off[g][dn] + atomicAdd(&g_cursor[g][dn], 1);
    g_csr[g][pos] = __ldg(s + e);
}

// Gather aggregation: y[n] = dinv[n] * sum_{s in inc(n)} dinv[s] * x[s].
// 16 threads per node, float4 per thread, register accumulation, one store.
__global__ void k_agg(int layer) {
    int idx  = blockIdx.x * blockDim.x + threadIdx.x;
    int slot = idx >> 4;                     // 0 .. 3*NN-1
    if (slot >= 3 * NN) return;
    int g = slot / NN;
    int n = slot - g * NN;
    int q = (idx & 15) * 4;

    const int*   csr = g_csr[g];
    const float* din = g_dinv[g];
    const float* xin = layer ? g_ping[g] : g_x0;
    float*       yo  = layer ? g_res[g]  : g_ping[g];

    int b  = __ldg(&g_off[g][n]);
    int e2 = __ldg(&g_off[g][n + 1]);
    float dn = din[n];

    float4 acc = make_float4(0.f, 0.f, 0.f, 0.f);
    int j = b;
    for (; j + 1 < e2; j += 2) {
        int s0 = __ldg(csr + j);
        int s1 = __ldg(csr + j + 1);
        float w0 = dn * __ldg(din + s0);
        float w1 = dn * __ldg(din + s1);
        float4 v0 = *(const float4*)(xin + s0 * DIM + q);
        float4 v1 = *(const float4*)(xin + s1 * DIM + q);
        acc.x += w0 * v0.x + w1 * v1.x;
        acc.y += w0 * v0.y + w1 * v1.y;
        acc.z += w0 * v0.z + w1 * v1.z;
        acc.w += w0 * v0.w + w1 * v1.w;
    }
    if (j < e2) {
        int s0 = __ldg(csr + j);
        float w0 = dn * __ldg(din + s0);
        float4 v0 = *(const float4*)(xin + s0 * DIM + q);
        acc.x += w0 * v0.x; acc.y += w0 * v0.y;
        acc.z += w0 * v0.z; acc.w += w0 * v0.w;
    }
    *(float4*)(yo + n * DIM + q) = acc;
}

// Fused: normalize each of the 3 results per row and weighted-combine.
__global__ void k_combine(const float* __restrict__ alpha, float* __restrict__ out) {
    int warp = (blockIdx.x * blockDim.x + threadIdx.x) >> 5;
    int lane = threadIdx.x & 31;
    if (warp >= NN) return;

    float a0 = alpha[0], a1 = alpha[1], a2 = alpha[2];
    float m  = fmaxf(a0, fmaxf(a1, a2));
    float e0 = expf(a0 - m), e1 = expf(a1 - m), e2 = expf(a2 - m);
    float s3 = e0 + e1 + e2;
    float w0 = fmaxf(e0 / s3, 1e-4f);
    float w1 = fmaxf(e1 / s3, 1e-4f);
    float w2 = fmaxf(e2 / s3, 1e-4f);
    float ws = w0 + w1 + w2;
    w0 /= ws; w1 /= ws; w2 /= ws;

    int off = warp * DIM + lane * 2;
    float2 va = *(const float2*)(g_res[0] + off);
    float2 vb = *(const float2*)(g_res[1] + off);
    float2 vc = *(const float2*)(g_res[2] + off);
    float sa = va.x * va.x + va.y * va.y;
    float sb = vb.x * vb.x + vb.y * vb.y;
    float sc = vc.x * vc.x + vc.y * vc.y;
    #pragma unroll
    for (int o = 16; o; o >>= 1) {
        sa += __shfl_xor_sync(0xFFFFFFFFu, sa, o);
        sb += __shfl_xor_sync(0xFFFFFFFFu, sb, o);
        sc += __shfl_xor_sync(0xFFFFFFFFu, sc, o);
    }
    float ia = 1.0f / fmaxf(sqrtf(sa), 1e-12f);
    float ib = 1.0f / fmaxf(sqrtf(sb), 1e-12f);
    float ic = 1.0f / fmaxf(sqrtf(sc), 1e-12f);

    float2 r;
    r.x = w0 * va.x * ia + w1 * vb.x * ib + w2 * vc.x * ic;
    r.y = w0 * va.y * ia + w1 * vb.y * ib + w2 * vc.y * ic;
    *(float2*)(out + off) = r;
}

// ---------------- launch ----------------
extern "C" void kernel_launch(void* const* d_in, const int* in_sizes, int n_in,
                              void* d_out, int out_size) {
    const float* x     = (const float*)d_in[0];
    const float* alpha = (const float*)d_in[1];
    const int*   s0 = (const int*)d_in[2], *d0 = s0 + NE;
    const int*   s1 = (const int*)d_in[3], *d1 = s1 + NE;
    const int*   s2 = (const int*)d_in[4], *d2 = s2 + NE;
    float* out = (float*)d_out;

    const int T = 256;
    const int gRows  = (NN * 32 + T - 1) / T;
    const int gZeroI = (3 * NN + T - 1) / T;
    const int gE3    = (3 * NE + T - 1) / T;
    const int gAgg   = (3 * NN * 16 + T - 1) / T;

    k_l2norm_in<<<gRows, T>>>(x);
    k_zero_int <<<gZeroI, T>>>();
    k_degree3  <<<gE3, T>>>(d0, d1, d2);
    k_scan     <<<3, 1024>>>();
    k_fill3    <<<gE3, T>>>(s0, d0, s1, d1, s2, d2);
    k_agg      <<<gAgg, T>>>(0);   // layer 1: x0 -> ping[g]
    k_agg      <<<gAgg, T>>>(1);   // layer 2: ping[g] -> res[g]
    k_combine  <<<gRows, T>>>(alpha, out);
}

// round 4
// speedup vs baseline: 3.9368x; 1.1604x over previous
#include <cuda_runtime.h>

#define NN 50000
#define DIM 64
#define NE 800000
#define TILE 1024
#define NT ((NN + TILE - 1) / TILE)   // 49 tiles per graph

// ---------------- scratch (allocation-free: device globals) ----------------
__device__ __align__(16) float g_x0  [NN * DIM];       // normalized input (shared by all graphs)
__device__ __align__(16) float g_ping[3][NN * DIM];    // layer-1 outputs
__device__ __align__(16) float g_res [3][NN * DIM];    // layer-2 outputs
__device__ int   g_degi  [3][NN];
__device__ int   g_cursor[3][NN];
__device__ int   g_off   [3][NN + 1];
__device__ float g_dinv  [3][NN];
__device__ int   g_csr   [3][NE];
__device__ int   g_tsum  [3][NT];
__device__ int   g_toff  [3][NT];

// ---------------- kernels ----------------

// L2-normalize input rows -> g_x0. One warp per row, 2 floats per lane.
__global__ void k_l2norm_in(const float* __restrict__ x) {
    int warp = (blockIdx.x * blockDim.x + threadIdx.x) >> 5;
    int lane = threadIdx.x & 31;
    if (warp >= NN) return;
    int off = warp * DIM + lane * 2;
    float2 v = *(const float2*)(x + off);
    float s = v.x * v.x + v.y * v.y;
    #pragma unroll
    for (int o = 16; o; o >>= 1) s += __shfl_xor_sync(0xFFFFFFFFu, s, o);
    float inv = 1.0f / fmaxf(sqrtf(s), 1e-12f);
    *(float2*)(g_x0 + off) = make_float2(v.x * inv, v.y * inv);
}

// Zero degree + cursor for all 3 graphs.
__global__ void k_zero_int() {
    int i = blockIdx.x * blockDim.x + threadIdx.x;
    if (i < 3 * NN) {
        ((int*)g_degi)[i]   = 0;
        ((int*)g_cursor)[i] = 0;
    }
}

// Degree of dst for all 3 graphs.
__global__ void k_degree3(const int* __restrict__ d0, const int* __restrict__ d1,
                          const int* __restrict__ d2) {
    int i = blockIdx.x * blockDim.x + threadIdx.x;
    if (i >= 3 * NE) return;
    int g = i / NE, e = i - g * NE;
    const int* d = (g == 0) ? d0 : (g == 1) ? d1 : d2;
    atomicAdd(&g_degi[g][__ldg(d + e)], 1);
}

// Phase 1: per-tile degree sums. One block per (graph, tile), 256 threads x 4 elems.
__global__ void k_tilesum() {
    int g = blockIdx.x / NT;
    int t = blockIdx.x - g * NT;
    int tid = threadIdx.x;
    int base = t * TILE + tid * 4;
    int s = 0;
    #pragma unroll
    for (int k = 0; k < 4; k++) {
        int i = base + k;
        if (i < NN) s += g_degi[g][i];
    }
    #pragma unroll
    for (int o = 16; o; o >>= 1) s += __shfl_xor_sync(0xFFFFFFFFu, s, o);
    __shared__ int wsum[8];
    if ((tid & 31) == 0) wsum[tid >> 5] = s;
    __syncthreads();
    if (tid < 8) {
        int v = wsum[tid];
        #pragma unroll
        for (int o = 4; o; o >>= 1) v += __shfl_xor_sync(0xFFu, v, o);
        if (tid == 0) g_tsum[g][t] = v;
    }
}

// Phase 2: serial scan of 49 tile sums per graph (3 threads total, trivial).
__global__ void k_tilescan() {
    int g = threadIdx.x;
    if (g >= 3) return;
    int acc = 0;
    for (int t = 0; t < NT; t++) {
        g_toff[g][t] = acc;
        acc += g_tsum[g][t];
    }
    g_off[g][NN] = acc;   // total edges (== NE)
}

// Phase 3: intra-tile exclusive scan + tile base -> g_off; also dinv.
__global__ void k_offsets() {
    int g = blockIdx.x / NT;
    int t = blockIdx.x - g * NT;
    int tid = threadIdx.x;           // 1024 threads
    int lane = tid & 31, wid = tid >> 5;
    int i = t * TILE + tid;
    int v = (i < NN) ? g_degi[g][i] : 0;

    int incl = v;
    #pragma unroll
    for (int o = 1; o < 32; o <<= 1) {
        int tt = __shfl_up_sync(0xFFFFFFFFu, incl, o);
        if (lane >= o) incl += tt;
    }
    __shared__ int wsum[32];
    if (lane == 31) wsum[wid] = incl;
    __syncthreads();
    if (wid == 0) {
        int sv = wsum[lane];
        #pragma unroll
        for (int o = 1; o < 32; o <<= 1) {
            int tt = __shfl_up_sync(0xFFFFFFFFu, sv, o);
            if (lane >= o) sv += tt;
        }
        wsum[lane] = sv;
    }
    __syncthreads();
    int warp_off = (wid > 0) ? wsum[wid - 1] : 0;
    if (i < NN) {
        g_off[g][i]  = g_toff[g][t] + warp_off + incl - v;
        g_dinv[g][i] = (v > 0) ? rsqrtf((float)v) : 0.f;
    }
}

// Counting-sort fill: csr[g][ off[dst] + cursor[dst]++ ] = src.
__global__ void k_fill3(const int* __restrict__ s0, const int* __restrict__ d0,
                        const int* __restrict__ s1, const int* __restrict__ d1,
                        const int* __restrict__ s2, const int* __restrict__ d2) {
    int i = blockIdx.x * blockDim.x + threadIdx.x;
    if (i >= 3 * NE) return;
    int g = i / NE, e = i - g * NE;
    const int* s = (g == 0) ? s0 : (g == 1) ? s1 : s2;
    const int* d = (g == 0) ? d0 : (g == 1) ? d1 : d2;
    int dn  = __ldg(d + e);
    int pos = g_off[g][dn] + atomicAdd(&g_cursor[g][dn], 1);
    g_csr[g][pos] = __ldg(s + e);
}

// Gather aggregation: y[n] = dinv[n] * sum_{s in inc(n)} dinv[s] * x[s].
// 16 threads per node, float4 per thread, register accumulation, one store.
__global__ void k_agg(int layer) {
    int idx  = blockIdx.x * blockDim.x + threadIdx.x;
    int slot = idx >> 4;                     // 0 .. 3*NN-1
    if (slot >= 3 * NN) return;
    int g = slot / NN;
    int n = slot - g * NN;
    int q = (idx & 15) * 4;

    const int*   csr = g_csr[g];
    const float* din = g_dinv[g];
    const float* xin = layer ? g_ping[g] : g_x0;
    float*       yo  = layer ? g_res[g]  : g_ping[g];

    int b  = __ldg(&g_off[g][n]);
    int e2 = __ldg(&g_off[g][n + 1]);
    float dn = din[n];

    float4 acc = make_float4(0.f, 0.f, 0.f, 0.f);
    int j = b;
    for (; j + 1 < e2; j += 2) {
        int s0 = __ldg(csr + j);
        int s1 = __ldg(csr + j + 1);
        float w0 = dn * __ldg(din + s0);
        float w1 = dn * __ldg(din + s1);
        float4 v0 = *(const float4*)(xin + s0 * DIM + q);
        float4 v1 = *(const float4*)(xin + s1 * DIM + q);
        acc.x += w0 * v0.x + w1 * v1.x;
        acc.y += w0 * v0.y + w1 * v1.y;
        acc.z += w0 * v0.z + w1 * v1.z;
        acc.w += w0 * v0.w + w1 * v1.w;
    }
    if (j < e2) {
        int s0 = __ldg(csr + j);
        float w0 = dn * __ldg(din + s0);
        float4 v0 = *(const float4*)(xin + s0 * DIM + q);
        acc.x += w0 * v0.x; acc.y += w0 * v0.y;
        acc.z += w0 * v0.z; acc.w += w0 * v0.w;
    }
    *(float4*)(yo + n * DIM + q) = acc;
}

// Fused: normalize each of the 3 results per row and weighted-combine.
__global__ void k_combine(const float* __restrict__ alpha, float* __restrict__ out) {
    int warp = (blockIdx.x * blockDim.x + threadIdx.x) >> 5;
    int lane = threadIdx.x & 31;
    if (warp >= NN) return;

    float a0 = alpha[0], a1 = alpha[1], a2 = alpha[2];
    float m  = fmaxf(a0, fmaxf(a1, a2));
    float e0 = expf(a0 - m), e1 = expf(a1 - m), e2 = expf(a2 - m);
    float s3 = e0 + e1 + e2;
    float w0 = fmaxf(e0 / s3, 1e-4f);
    float w1 = fmaxf(e1 / s3, 1e-4f);
    float w2 = fmaxf(e2 / s3, 1e-4f);
    float ws = w0 + w1 + w2;
    w0 /= ws; w1 /= ws; w2 /= ws;

    int off = warp * DIM + lane * 2;
    float2 va = *(const float2*)(g_res[0] + off);
    float2 vb = *(const float2*)(g_res[1] + off);
    float2 vc = *(const float2*)(g_res[2] + off);
    float sa = va.x * va.x + va.y * va.y;
    float sb = vb.x * vb.x + vb.y * vb.y;
    float sc = vc.x * vc.x + vc.y * vc.y;
    #pragma unroll
    for (int o = 16; o; o >>= 1) {
        sa += __shfl_xor_sync(0xFFFFFFFFu, sa, o);
        sb += __shfl_xor_sync(0xFFFFFFFFu, sb, o);
        sc += __shfl_xor_sync(0xFFFFFFFFu, sc, o);
    }
    float ia = 1.0f / fmaxf(sqrtf(sa), 1e-12f);
    float ib = 1.0f / fmaxf(sqrtf(sb), 1e-12f);
    float ic = 1.0f / fmaxf(sqrtf(sc), 1e-12f);

    float2 r;
    r.x = w0 * va.x * ia + w1 * vb.x * ib + w2 * vc.x * ic;
    r.y = w0 * va.y * ia + w1 * vb.y * ib + w2 * vc.y * ic;
    *(float2*)(out + off) = r;
}

// ---------------- launch ----------------
extern "C" void kernel_launch(void* const* d_in, const int* in_sizes, int n_in,
                              void* d_out, int out_size) {
    const float* x     = (const float*)d_in[0];
    const float* alpha = (const float*)d_in[1];
    const int*   s0 = (const int*)d_in[2], *d0 = s0 + NE;
    const int*   s1 = (const int*)d_in[3], *d1 = s1 + NE;
    const int*   s2 = (const int*)d_in[4], *d2 = s2 + NE;
    float* out = (float*)d_out;

    const int T = 256;
    const int gRows  = (NN * 32 + T - 1) / T;
    const int gZeroI = (3 * NN + T - 1) / T;
    const int gE3    = (3 * NE + T - 1) / T;
    const int gAgg   = (3 * NN * 16 + T - 1) / T;

    k_l2norm_in<<<gRows, T>>>(x);
    k_zero_int <<<gZeroI, T>>>();
    k_degree3  <<<gE3, T>>>(d0, d1, d2);
    k_tilesum  <<<3 * NT, 256>>>();
    k_tilescan <<<1, 32>>>();
    k_offsets  <<<3 * NT, TILE>>>();
    k_fill3    <<<gE3, T>>>(s0, d0, s1, d1, s2, d2);
    k_agg      <<<gAgg, T>>>(0);   // layer 1: x0 -> ping[g]
    k_agg      <<<gAgg, T>>>(1);   // layer 2: ping[g] -> res[g]
    k_combine  <<<gRows, T>>>(alpha, out);
}

// round 5
// speedup vs baseline: 4.7747x; 1.2128x over previous
#include <cuda_runtime.h>
#include <cuda_fp16.h>

#define NN 50000
#define DIM 64
#define NE 800000
#define TILE 1024
#define NT ((NN + TILE - 1) / TILE)   // 49 tiles per graph

// ---------------- scratch (allocation-free: device globals) ----------------
__device__ __align__(16) __half g_xh  [NN * DIM];       // normalized input, fp16
__device__ __align__(16) __half g_pingh[3][NN * DIM];   // layer-1 outputs, fp16
__device__ __align__(16) float  g_res [3][NN * DIM];    // layer-2 outputs, fp32
__device__ int   g_degi  [3][NN];
__device__ int   g_cursor[3][NN];
__device__ int   g_off   [3][NN + 1];
__device__ float g_dinv  [3][NN];
__device__ int   g_csr   [3][NE];
__device__ int   g_tsum  [3][NT];

// ---------------- kernels ----------------

// L2-normalize input rows -> g_xh (fp16). One warp per row, 2 floats per lane.
__global__ void k_l2norm_in(const float* __restrict__ x) {
    int warp = (blockIdx.x * blockDim.x + threadIdx.x) >> 5;
    int lane = threadIdx.x & 31;
    if (warp >= NN) return;
    int off = warp * DIM + lane * 2;
    float2 v = *(const float2*)(x + off);
    float s = v.x * v.x + v.y * v.y;
    #pragma unroll
    for (int o = 16; o; o >>= 1) s += __shfl_xor_sync(0xFFFFFFFFu, s, o);
    float inv = 1.0f / fmaxf(sqrtf(s), 1e-12f);
    __half2 h = __float22half2_rn(make_float2(v.x * inv, v.y * inv));
    *(__half2*)(g_xh + off) = h;
}

// Zero degree for all 3 graphs.
__global__ void k_zero_deg() {
    int i = blockIdx.x * blockDim.x + threadIdx.x;
    if (i < 3 * NN) ((int*)g_degi)[i] = 0;
}

// Degree of dst for all 3 graphs.
__global__ void k_degree3(const int* __restrict__ d0, const int* __restrict__ d1,
                          const int* __restrict__ d2) {
    int i = blockIdx.x * blockDim.x + threadIdx.x;
    if (i >= 3 * NE) return;
    int g = i / NE, e = i - g * NE;
    const int* d = (g == 0) ? d0 : (g == 1) ? d1 : d2;
    atomicAdd(&g_degi[g][__ldg(d + e)], 1);
}

// Phase 1: per-tile degree sums. One block per (graph, tile).
__global__ void k_tilesum() {
    int g = blockIdx.x / NT;
    int t = blockIdx.x - g * NT;
    int tid = threadIdx.x;
    int base = t * TILE + tid * 4;
    int s = 0;
    #pragma unroll
    for (int k = 0; k < 4; k++) {
        int i = base + k;
        if (i < NN) s += g_degi[g][i];
    }
    #pragma unroll
    for (int o = 16; o; o >>= 1) s += __shfl_xor_sync(0xFFFFFFFFu, s, o);
    __shared__ int wsum[8];
    if ((tid & 31) == 0) wsum[tid >> 5] = s;
    __syncthreads();
    if (tid < 8) {
        int v = wsum[tid];
        #pragma unroll
        for (int o = 4; o; o >>= 1) v += __shfl_xor_sync(0xFFu, v, o);
        if (tid == 0) g_tsum[g][t] = v;
    }
}

// Phase 2+3: each block sums tile sums below it (<=49 adds), intra-tile scan,
// writes g_off + dinv, zeroes cursor.
__global__ void k_offsets() {
    int g = blockIdx.x / NT;
    int t = blockIdx.x - g * NT;
    int tid = threadIdx.x;           // 1024 threads
    int lane = tid & 31, wid = tid >> 5;
    int i = t * TILE + tid;
    int v = (i < NN) ? g_degi[g][i] : 0;

    // tile base: serial sum over preceding tiles (compute in warp 0, broadcast)
    __shared__ int s_base;
    if (tid < 32) {
        int acc = 0;
        for (int k = lane; k < t; k += 32) acc += g_tsum[g][k];
        #pragma unroll
        for (int o = 16; o; o >>= 1) acc += __shfl_xor_sync(0xFFFFFFFFu, acc, o);
        if (lane == 0) s_base = acc;
    }

    int incl = v;
    #pragma unroll
    for (int o = 1; o < 32; o <<= 1) {
        int tt = __shfl_up_sync(0xFFFFFFFFu, incl, o);
        if (lane >= o) incl += tt;
    }
    __shared__ int wsum[32];
    if (lane == 31) wsum[wid] = incl;
    __syncthreads();
    if (wid == 0) {
        int sv = wsum[lane];
        #pragma unroll
        for (int o = 1; o < 32; o <<= 1) {
            int tt = __shfl_up_sync(0xFFFFFFFFu, sv, o);
            if (lane >= o) sv += tt;
        }
        wsum[lane] = sv;
    }
    __syncthreads();
    int warp_off = (wid > 0) ? wsum[wid - 1] : 0;
    if (i < NN) {
        g_off[g][i]    = s_base + warp_off + incl - v;
        g_dinv[g][i]   = (v > 0) ? rsqrtf((float)v) : 0.f;
        g_cursor[g][i] = 0;
    }
    if (t == NT - 1 && tid == 0) g_off[g][NN] = s_base + wsum[31];
}

// Counting-sort fill: csr[g][ off[dst] + cursor[dst]++ ] = src.
__global__ void k_fill3(const int* __restrict__ s0, const int* __restrict__ d0,
                        const int* __restrict__ s1, const int* __restrict__ d1,
                        const int* __restrict__ s2, const int* __restrict__ d2) {
    int i = blockIdx.x * blockDim.x + threadIdx.x;
    if (i >= 3 * NE) return;
    int g = i / NE, e = i - g * NE;
    const int* s = (g == 0) ? s0 : (g == 1) ? s1 : s2;
    const int* d = (g == 0) ? d0 : (g == 1) ? d1 : d2;
    int dn  = __ldg(d + e);
    int pos = g_off[g][dn] + atomicAdd(&g_cursor[g][dn], 1);
    g_csr[g][pos] = __ldg(s + e);
}

// Gather aggregation over fp16 features, fp32 accumulation.
// 8 threads per node, 8 dims (16 B of halfs) per thread.
// layer 0: g_xh -> g_pingh[g] (fp16 out); layer 1: g_pingh[g] -> g_res[g] (fp32 out).
__global__ void k_agg(int layer) {
    int idx  = blockIdx.x * blockDim.x + threadIdx.x;
    int slot = idx >> 3;                     // 0 .. 3*NN-1
    if (slot >= 3 * NN) return;
    int g = slot / NN;
    int n = slot - g * NN;
    int q = (idx & 7) * 8;                   // dim offset (halfs)

    const int*    csr = g_csr[g];
    const float*  din = g_dinv[g];
    const __half* xin = layer ? g_pingh[g] : g_xh;

    int b  = __ldg(&g_off[g][n]);
    int e2 = __ldg(&g_off[g][n + 1]);
    float dn = din[n];

    float2 acc[4] = { {0.f,0.f}, {0.f,0.f}, {0.f,0.f}, {0.f,0.f} };
    int j = b;
    for (; j + 1 < e2; j += 2) {
        int s0 = __ldg(csr + j);
        int s1 = __ldg(csr + j + 1);
        float w0 = dn * __ldg(din + s0);
        float w1 = dn * __ldg(din + s1);
        float4 r0 = *(const float4*)(xin + s0 * DIM + q);
        float4 r1 = *(const float4*)(xin + s1 * DIM + q);
        const __half2* h0 = (const __half2*)&r0;
        const __half2* h1 = (const __half2*)&r1;
        #pragma unroll
        for (int k = 0; k < 4; k++) {
            float2 f0 = __half22float2(h0[k]);
            float2 f1 = __half22float2(h1[k]);
            acc[k].x += w0 * f0.x + w1 * f1.x;
            acc[k].y += w0 * f0.y + w1 * f1.y;
        }
    }
    if (j < e2) {
        int s0 = __ldg(csr + j);
        float w0 = dn * __ldg(din + s0);
        float4 r0 = *(const float4*)(xin + s0 * DIM + q);
        const __half2* h0 = (const __half2*)&r0;
        #pragma unroll
        for (int k = 0; k < 4; k++) {
            float2 f0 = __half22float2(h0[k]);
            acc[k].x += w0 * f0.x;
            acc[k].y += w0 * f0.y;
        }
    }

    if (layer == 0) {
        __half2 outh[4];
        #pragma unroll
        for (int k = 0; k < 4; k++) outh[k] = __float22half2_rn(acc[k]);
        *(float4*)(g_pingh[g] + n * DIM + q) = *(float4*)outh;
    } else {
        float* yo = g_res[g] + n * DIM + q;
        *(float4*)(yo + 0) = make_float4(acc[0].x, acc[0].y, acc[1].x, acc[1].y);
        *(float4*)(yo + 4) = make_float4(acc[2].x, acc[2].y, acc[3].x, acc[3].y);
    }
}

// Fused: normalize each of the 3 results per row and weighted-combine.
__global__ void k_combine(const float* __restrict__ alpha, float* __restrict__ out) {
    int warp = (blockIdx.x * blockDim.x + threadIdx.x) >> 5;
    int lane = threadIdx.x & 31;
    if (warp >= NN) return;

    float a0 = alpha[0], a1 = alpha[1], a2 = alpha[2];
    float m  = fmaxf(a0, fmaxf(a1, a2));
    float e0 = expf(a0 - m), e1 = expf(a1 - m), e2 = expf(a2 - m);
    float s3 = e0 + e1 + e2;
    float w0 = fmaxf(e0 / s3, 1e-4f);
    float w1 = fmaxf(e1 / s3, 1e-4f);
    float w2 = fmaxf(e2 / s3, 1e-4f);
    float ws = w0 + w1 + w2;
    w0 /= ws; w1 /= ws; w2 /= ws;

    int off = warp * DIM + lane * 2;
    float2 va = *(const float2*)(g_res[0] + off);
    float2 vb = *(const float2*)(g_res[1] + off);
    float2 vc = *(const float2*)(g_res[2] + off);
    float sa = va.x * va.x + va.y * va.y;
    float sb = vb.x * vb.x + vb.y * vb.y;
    float sc = vc.x * vc.x + vc.y * vc.y;
    #pragma unroll
    for (int o = 16; o; o >>= 1) {
        sa += __shfl_xor_sync(0xFFFFFFFFu, sa, o);
        sb += __shfl_xor_sync(0xFFFFFFFFu, sb, o);
        sc += __shfl_xor_sync(0xFFFFFFFFu, sc, o);
    }
    float ia = 1.0f / fmaxf(sqrtf(sa), 1e-12f);
    float ib = 1.0f / fmaxf(sqrtf(sb), 1e-12f);
    float ic = 1.0f / fmaxf(sqrtf(sc), 1e-12f);

    float2 r;
    r.x = w0 * va.x * ia + w1 * vb.x * ib + w2 * vc.x * ic;
    r.y = w0 * va.y * ia + w1 * vb.y * ib + w2 * vc.y * ic;
    *(float2*)(out + off) = r;
}

// ---------------- launch ----------------
extern "C" void kernel_launch(void* const* d_in, const int* in_sizes, int n_in,
                              void* d_out, int out_size) {
    const float* x     = (const float*)d_in[0];
    const float* alpha = (const float*)d_in[1];
    const int*   s0 = (const int*)d_in[2], *d0 = s0 + NE;
    const int*   s1 = (const int*)d_in[3], *d1 = s1 + NE;
    const int*   s2 = (const int*)d_in[4], *d2 = s2 + NE;
    float* out = (float*)d_out;

    const int T = 256;
    const int gRows  = (NN * 32 + T - 1) / T;
    const int gZeroI = (3 * NN + T - 1) / T;
    const int gE3    = (3 * NE + T - 1) / T;
    const int gAgg   = (3 * NN * 8 + T - 1) / T;

    k_l2norm_in<<<gRows, T>>>(x);
    k_zero_deg <<<gZeroI, T>>>();
    k_degree3  <<<gE3, T>>>(d0, d1, d2);
    k_tilesum  <<<3 * NT, 256>>>();
    k_offsets  <<<3 * NT, TILE>>>();
    k_fill3    <<<gE3, T>>>(s0, d0, s1, d1, s2, d2);
    k_agg      <<<gAgg, T>>>(0);   // layer 1: xh -> pingh[g]
    k_agg      <<<gAgg, T>>>(1);   // layer 2: pingh[g] -> res[g]
    k_combine  <<<gRows, T>>>(alpha, out);
}

// round 6
// speedup vs baseline: 5.3315x; 1.1166x over previous
#include <cuda_runtime.h>
#include <cuda_fp16.h>

#define NN 50000
#define DIM 64
#define NE 800000
#define TILE 1024
#define NT ((NN + TILE - 1) / TILE)   // 49 tiles per graph

// ---------------- scratch (allocation-free: device globals) ----------------
__device__ __align__(16) __half g_xh   [NN * DIM];      // normalized input, fp16
__device__ __align__(16) __half g_pingh[3][NN * DIM];   // layer-1 outputs, fp16
__device__ __align__(16) __half g_resh [3][NN * DIM];   // layer-2 outputs, fp16
__device__ int   g_degi  [3][NN];
__device__ int   g_cursor[3][NN];
__device__ int   g_off   [3][NN + 1];
__device__ float g_dinv  [3][NN];
__device__ int   g_csr   [3][NE];
__device__ int   g_tsum  [3][NT];

// ---------------- kernels ----------------

// L2-normalize input rows -> g_xh (fp16). One warp per row, 2 floats per lane.
__global__ void k_l2norm_in(const float* __restrict__ x) {
    int warp = (blockIdx.x * blockDim.x + threadIdx.x) >> 5;
    int lane = threadIdx.x & 31;
    if (warp >= NN) return;
    int off = warp * DIM + lane * 2;
    float2 v = *(const float2*)(x + off);
    float s = v.x * v.x + v.y * v.y;
    #pragma unroll
    for (int o = 16; o; o >>= 1) s += __shfl_xor_sync(0xFFFFFFFFu, s, o);
    float inv = 1.0f / fmaxf(sqrtf(s), 1e-12f);
    *(__half2*)(g_xh + off) = __float22half2_rn(make_float2(v.x * inv, v.y * inv));
}

__global__ void k_zero_deg_g(int g) {
    int i = blockIdx.x * blockDim.x + threadIdx.x;
    if (i < NN) g_degi[g][i] = 0;
}

__global__ void k_degree_g(const int* __restrict__ dst, int g) {
    int e = blockIdx.x * blockDim.x + threadIdx.x;
    if (e < NE) atomicAdd(&g_degi[g][__ldg(dst + e)], 1);
}

// Per-tile degree sums (one block per tile).
__global__ void k_tilesum_g(int g) {
    int t = blockIdx.x;
    int tid = threadIdx.x;
    int base = t * TILE + tid * 4;
    int s = 0;
    #pragma unroll
    for (int k = 0; k < 4; k++) {
        int i = base + k;
        if (i < NN) s += g_degi[g][i];
    }
    #pragma unroll
    for (int o = 16; o; o >>= 1) s += __shfl_xor_sync(0xFFFFFFFFu, s, o);
    __shared__ int wsum[8];
    if ((tid & 31) == 0) wsum[tid >> 5] = s;
    __syncthreads();
    if (tid < 8) {
        int v = wsum[tid];
        #pragma unroll
        for (int o = 4; o; o >>= 1) v += __shfl_xor_sync(0xFFu, v, o);
        if (tid == 0) g_tsum[g][t] = v;
    }
}

// Tile base (serial sum of preceding tile sums) + intra-tile scan.
// Writes g_off, g_dinv, and g_cursor := off (cursor-as-offset trick).
__global__ void k_offsets_g(int g) {
    int t = blockIdx.x;
    int tid = threadIdx.x;           // 1024
    int lane = tid & 31, wid = tid >> 5;
    int i = t * TILE + tid;
    int v = (i < NN) ? g_degi[g][i] : 0;

    __shared__ int s_base;
    if (tid < 32) {
        int acc = 0;
        for (int k = lane; k < t; k += 32) acc += g_tsum[g][k];
        #pragma unroll
        for (int o = 16; o; o >>= 1) acc += __shfl_xor_sync(0xFFFFFFFFu, acc, o);
        if (lane == 0) s_base = acc;
    }

    int incl = v;
    #pragma unroll
    for (int o = 1; o < 32; o <<= 1) {
        int tt = __shfl_up_sync(0xFFFFFFFFu, incl, o);
        if (lane >= o) incl += tt;
    }
    __shared__ int wsum[32];
    if (lane == 31) wsum[wid] = incl;
    __syncthreads();
    if (wid == 0) {
        int sv = wsum[lane];
        #pragma unroll
        for (int o = 1; o < 32; o <<= 1) {
            int tt = __shfl_up_sync(0xFFFFFFFFu, sv, o);
            if (lane >= o) sv += tt;
        }
        wsum[lane] = sv;
    }
    __syncthreads();
    int warp_off = (wid > 0) ? wsum[wid - 1] : 0;
    if (i < NN) {
        int off = s_base + warp_off + incl - v;
        g_off[g][i]    = off;
        g_cursor[g][i] = off;
        g_dinv[g][i]   = (v > 0) ? rsqrtf((float)v) : 0.f;
    }
    if (t == NT - 1 && tid == 0) g_off[g][NN] = s_base + wsum[31];
}

// Counting-sort fill: csr[g][ cursor[dst]++ ] = src.
__global__ void k_fill_g(const int* __restrict__ src, const int* __restrict__ dst, int g) {
    int e = blockIdx.x * blockDim.x + threadIdx.x;
    if (e >= NE) return;
    int dn  = __ldg(dst + e);
    int pos = atomicAdd(&g_cursor[g][dn], 1);
    g_csr[g][pos] = __ldg(src + e);
}

// Gather aggregation over fp16 features, fp32 accumulation, fp16 output.
// 8 threads per node, 8 dims (16 B) per thread.
__global__ void k_agg_g(int g, int layer) {
    int idx = blockIdx.x * blockDim.x + threadIdx.x;
    int n   = idx >> 3;
    if (n >= NN) return;
    int q = (idx & 7) * 8;

    const int*    csr = g_csr[g];
    const float*  din = g_dinv[g];
    const __half* xin = layer ? g_pingh[g] : g_xh;
    __half*       yo  = layer ? g_resh[g]  : g_pingh[g];

    int b  = __ldg(&g_off[g][n]);
    int e2 = __ldg(&g_off[g][n + 1]);
    float dn = din[n];

    float2 acc[4] = { {0.f,0.f}, {0.f,0.f}, {0.f,0.f}, {0.f,0.f} };
    int j = b;
    for (; j + 1 < e2; j += 2) {
        int s0 = __ldg(csr + j);
        int s1 = __ldg(csr + j + 1);
        float w0 = dn * __ldg(din + s0);
        float w1 = dn * __ldg(din + s1);
        float4 r0 = *(const float4*)(xin + s0 * DIM + q);
        float4 r1 = *(const float4*)(xin + s1 * DIM + q);
        const __half2* h0 = (const __half2*)&r0;
        const __half2* h1 = (const __half2*)&r1;
        #pragma unroll
        for (int k = 0; k < 4; k++) {
            float2 f0 = __half22float2(h0[k]);
            float2 f1 = __half22float2(h1[k]);
            acc[k].x += w0 * f0.x + w1 * f1.x;
            acc[k].y += w0 * f0.y + w1 * f1.y;
        }
    }
    if (j < e2) {
        int s0 = __ldg(csr + j);
        float w0 = dn * __ldg(din + s0);
        float4 r0 = *(const float4*)(xin + s0 * DIM + q);
        const __half2* h0 = (const __half2*)&r0;
        #pragma unroll
        for (int k = 0; k < 4; k++) {
            float2 f0 = __half22float2(h0[k]);
            acc[k].x += w0 * f0.x;
            acc[k].y += w0 * f0.y;
        }
    }

    __half2 outh[4];
    #pragma unroll
    for (int k = 0; k < 4; k++) outh[k] = __float22half2_rn(acc[k]);
    *(float4*)(yo + n * DIM + q) = *(float4*)outh;
}

// Fused: normalize each of the 3 fp16 results per row and weighted-combine (fp32 out).
__global__ void k_combine(const float* __restrict__ alpha, float* __restrict__ out) {
    int warp = (blockIdx.x * blockDim.x + threadIdx.x) >> 5;
    int lane = threadIdx.x & 31;
    if (warp >= NN) return;

    float a0 = alpha[0], a1 = alpha[1], a2 = alpha[2];
    float m  = fmaxf(a0, fmaxf(a1, a2));
    float e0 = expf(a0 - m), e1 = expf(a1 - m), e2 = expf(a2 - m);
    float s3 = e0 + e1 + e2;
    float w0 = fmaxf(e0 / s3, 1e-4f);
    float w1 = fmaxf(e1 / s3, 1e-4f);
    float w2 = fmaxf(e2 / s3, 1e-4f);
    float ws = w0 + w1 + w2;
    w0 /= ws; w1 /= ws; w2 /= ws;

    int off = warp * DIM + lane * 2;
    float2 va = __half22float2(*(const __half2*)(g_resh[0] + off));
    float2 vb = __half22float2(*(const __half2*)(g_resh[1] + off));
    float2 vc = __half22float2(*(const __half2*)(g_resh[2] + off));
    float sa = va.x * va.x + va.y * va.y;
    float sb = vb.x * vb.x + vb.y * vb.y;
    float sc = vc.x * vc.x + vc.y * vc.y;
    #pragma unroll
    for (int o = 16; o; o >>= 1) {
        sa += __shfl_xor_sync(0xFFFFFFFFu, sa, o);
        sb += __shfl_xor_sync(0xFFFFFFFFu, sb, o);
        sc += __shfl_xor_sync(0xFFFFFFFFu, sc, o);
    }
    float ia = 1.0f / fmaxf(sqrtf(sa), 1e-12f);
    float ib = 1.0f / fmaxf(sqrtf(sb), 1e-12f);
    float ic = 1.0f / fmaxf(sqrtf(sc), 1e-12f);

    float2 r;
    r.x = w0 * va.x * ia + w1 * vb.x * ib + w2 * vc.x * ic;
    r.y = w0 * va.y * ia + w1 * vb.y * ib + w2 * vc.y * ic;
    *(float2*)(out + off) = r;
}

// ---------------- launch ----------------
extern "C" void kernel_launch(void* const* d_in, const int* in_sizes, int n_in,
                              void* d_out, int out_size) {
    const float* x     = (const float*)d_in[0];
    const float* alpha = (const float*)d_in[1];
    const int*   srcs[3] = { (const int*)d_in[2], (const int*)d_in[3], (const int*)d_in[4] };
    float* out = (float*)d_out;

    // One-time host-side stream/event setup (no device memory involved).
    static cudaStream_t st[3];
    static cudaEvent_t  evFork, evX, evDone[3];
    static bool inited = false;
    if (!inited) {
        for (int g = 0; g < 3; g++)
            cudaStreamCreateWithFlags(&st[g], cudaStreamNonBlocking);
        cudaEventCreateWithFlags(&evFork, cudaEventDisableTiming);
        cudaEventCreateWithFlags(&evX,    cudaEventDisableTiming);
        for (int g = 0; g < 3; g++)
            cudaEventCreateWithFlags(&evDone[g], cudaEventDisableTiming);
        inited = true;
    }

    const int T = 256;
    const int gRows  = (NN * 32 + T - 1) / T;
    const int gNode  = (NN + T - 1) / T;
    const int gEdge  = (NE + T - 1) / T;
    const int gAgg   = (NN * 8 + T - 1) / T;

    // Fork per-graph CSR-build pipelines off the main stream.
    cudaEventRecord(evFork, 0);
    for (int g = 0; g < 3; g++)
        cudaStreamWaitEvent(st[g], evFork, 0);

    // Main stream: normalize input (independent of CSR builds).
    k_l2norm_in<<<gRows, T>>>(x);
    cudaEventRecord(evX, 0);

    for (int g = 0; g < 3; g++) {
        const int* src = srcs[g];
        const int* dst = srcs[g] + NE;
        k_zero_deg_g<<<gNode, T, 0, st[g]>>>(g);
        k_degree_g  <<<gEdge, T, 0, st[g]>>>(dst, g);
        k_tilesum_g <<<NT, 256, 0, st[g]>>>(g);
        k_offsets_g <<<NT, TILE, 0, st[g]>>>(g);
        k_fill_g    <<<gEdge, T, 0, st[g]>>>(src, dst, g);
        cudaStreamWaitEvent(st[g], evX, 0);            // need g_xh for layer 1
        k_agg_g     <<<gAgg, T, 0, st[g]>>>(g, 0);     // xh -> pingh[g]
        k_agg_g     <<<gAgg, T, 0, st[g]>>>(g, 1);     // pingh[g] -> resh[g]
        cudaEventRecord(evDone[g], st[g]);
    }

    for (int g = 0; g < 3; g++)
        cudaStreamWaitEvent(0, evDone[g], 0);
    k_combine<<<gRows, T>>>(alpha, out);
}